// round 15
// baseline (speedup 1.0000x reference)
#include <cuda_runtime.h>
#include <cuda_bf16.h>
#include <cstdint>

// ---------------------------------------------------------------------------
// Shapes: b=4, h=8, l=1024, d=64. Per-batch flat matrix M: 1024 x 512.
// Outputs: context (4,8,1024,64) then attn_out (4,8,4,1024).
// ---------------------------------------------------------------------------

__device__ float  g_cre[2 * 4 * 1024 * 512];
__device__ float  g_cim[2 * 4 * 1024 * 512];
__device__ float  g_Mq [4 * 1024 * 512];
__device__ float  g_Mk [4 * 1024 * 512];
// bf16 split P tensors, layout [bh*4+p][l(1024)][d(64)], d contiguous
__device__ __nv_bfloat16 g_Qhi[32 * 4 * 1024 * 64];
__device__ __nv_bfloat16 g_Qlo[32 * 4 * 1024 * 64];
__device__ __nv_bfloat16 g_Khi[32 * 4 * 1024 * 64];
__device__ __nv_bfloat16 g_Klo[32 * 4 * 1024 * 64];

// ---------------------------------------------------------------------------
// Stage 1: 512-pt FFT along each contiguous row (smem twiddle LUT).
// ---------------------------------------------------------------------------
__global__ void fft512_rows(const float* __restrict__ Qin,
                            const float* __restrict__ Kin) {
    __shared__ float re[512], im[512];
    __shared__ float2 tw[512];
    int R = blockIdx.x;                        // 0..8191
    const float* src = (R < 4096) ? Qin : Kin;
    const float* row = src + (size_t)(R & 4095) * 512;
    int t = threadIdx.x;  // 256
    for (int i = t; i < 512; i += 256) {
        re[i] = row[__brev((unsigned)i) >> 23];
        im[i] = 0.f;
        float si, co;
        sincospif(-(float)i / 512.f, &si, &co);
        tw[i] = make_float2(co, si);
    }
    __syncthreads();
    for (int s = 0; s < 9; s++) {
        int hl = 1 << s;
        int pos = t & (hl - 1);
        int i0 = ((t >> s) << (s + 1)) + pos;
        int i1 = i0 + hl;
        float2 w = tw[pos << (9 - s)];
        float xr = re[i1], xi = im[i1];
        float tr = w.x * xr - w.y * xi;
        float ti = w.x * xi + w.y * xr;
        float ur = re[i0], ui = im[i0];
        re[i0] = ur + tr; im[i0] = ui + ti;
        re[i1] = ur - tr; im[i1] = ui - ti;
        __syncthreads();
    }
    float* cr = g_cre + (size_t)R * 512;
    float* ci = g_cim + (size_t)R * 512;
    for (int i = t; i < 512; i += 256) { cr[i] = re[i]; ci[i] = im[i]; }
}

// ---------------------------------------------------------------------------
// Stage 2: 1024-pt FFT along columns, keep real part (smem twiddle LUT).
// ---------------------------------------------------------------------------
__global__ void fft1024_cols() {
    __shared__ float re[4096], im[4096];
    __shared__ float2 tw[512];
    int t = threadIdx.x;                 // 512
    int bi2 = blockIdx.x >> 7;           // 0..7 = which*4 + b
    int j0  = (blockIdx.x & 127) << 2;
    size_t gb = (size_t)bi2 << 19;
    {
        float si, co;
        sincospif(-(float)t / 512.f, &si, &co);
        tw[t] = make_float2(co, si);
    }
    for (int idx = t; idx < 4096; idx += 512) {
        int r = idx >> 2, c = idx & 3;
        int rv = __brev((unsigned)r) >> 22;
        size_t a = gb + (size_t)rv * 512 + j0 + c;
        re[idx] = g_cre[a];
        im[idx] = g_cim[a];
    }
    __syncthreads();
    for (int s = 0; s < 10; s++) {
        for (int u = t; u < 2048; u += 512) {
            int c = u & 3, jb = u >> 2;
            int hl = 1 << s;
            int pos = jb & (hl - 1);
            int i0 = ((jb >> s) << (s + 1)) + pos;
            int i1 = i0 + hl;
            float2 w = tw[pos << (9 - s)];
            int a0 = (i0 << 2) + c, a1 = (i1 << 2) + c;
            float xr = re[a1], xi = im[a1];
            float tr = w.x * xr - w.y * xi;
            float ti = w.x * xi + w.y * xr;
            float ur = re[a0], ui = im[a0];
            re[a0] = ur + tr; im[a0] = ui + ti;
            re[a1] = ur - tr; im[a1] = ui - ti;
        }
        __syncthreads();
    }
    float* M = (bi2 >= 4) ? g_Mk : g_Mq;
    size_t mb = (size_t)(bi2 & 3) << 19;
    for (int idx = t; idx < 4096; idx += 512) {
        int r = idx >> 2, c = idx & 3;
        M[mb + (size_t)r * 512 + j0 + c] = re[idx];
    }
}

// ---------------------------------------------------------------------------
// Multi-scale stencil, smem-staged, 4 r_o per block. Emits bf16 hi/lo split,
// transposed to [bh*4+p][l][d] layout (d contiguous) for HMMA fragments.
// ---------------------------------------------------------------------------
template <int C>
__device__ __forceinline__ float stencilS(const float* __restrict__ tile,
                                          const float* __restrict__ w,
                                          int r_o, int jp, int d2, int rr0) {
    float acc = 0.f;
#pragma unroll
    for (int ci = 0; ci < C; ci++) {
        int tt  = 64 * ci + d2;
        int il  = 9 - C + (tt % C);
        int col = jp + (tt / C) - C;
        if ((r_o - 9 + il) >= 0 && col >= 0)
            acc = fmaf(__ldg(w + ci), tile[(rr0 + il) * 513 + col], acc);
    }
    return acc;
}

__global__ void __launch_bounds__(512) multiscale(
    const float* __restrict__ wq1, const float* __restrict__ bq1,
    const float* __restrict__ wq3, const float* __restrict__ bq3,
    const float* __restrict__ wq6, const float* __restrict__ bq6,
    const float* __restrict__ wq9, const float* __restrict__ bq9,
    const float* __restrict__ wk1, const float* __restrict__ bk1,
    const float* __restrict__ wk3, const float* __restrict__ bk3,
    const float* __restrict__ wk6, const float* __restrict__ bk6,
    const float* __restrict__ wk9, const float* __restrict__ bk9) {
    __shared__ float tile[12 * 513];
    __shared__ float sbuf[4 * 64 * 9];
    int t   = threadIdx.x;
    int d2  = t & 63;
    int l2i = (t >> 6) & 7;
    int bx4 = blockIdx.x;                      // 0..31
    int bh  = blockIdx.y;
    int which = blockIdx.z;
    int b = bh >> 3, hi = bh & 7;

    const float* M = which ? g_Mk : g_Mq;
    __nv_bfloat16* Phi = which ? g_Khi : g_Qhi;
    __nv_bfloat16* Plo = which ? g_Klo : g_Qlo;
    const float* w1 = which ? wk1 : wq1;  const float* b1 = which ? bk1 : bq1;
    const float* w3 = which ? wk3 : wq3;  const float* b3 = which ? bk3 : bq3;
    const float* w6 = which ? wk6 : wq6;  const float* b6 = which ? bk6 : bq6;
    const float* w9 = which ? wk9 : wq9;  const float* b9 = which ? bk9 : bq9;
    float scale = which ? 1.0f : 0.125f;

    const float* Mb = M + ((size_t)b << 19);
    int r_o0 = (hi << 7) + bx4 * 4;
    int jp   = l2i << 6;

    for (int i = t; i < 12 * 512; i += 512) {
        int rr = i >> 9, cc = i & 511;
        int grow = r_o0 - 9 + rr;
        tile[rr * 513 + cc] = (grow >= 0) ? __ldg(Mb + grow * 512 + cc) : 0.f;
    }
    __syncthreads();

#pragma unroll
    for (int rr0 = 0; rr0 < 4; rr0++) {
        int r_o = r_o0 + rr0;
        float v0 = (__ldg(b1) + stencilS<1>(tile, w1, r_o, jp, d2, rr0)) * scale;
        float v1 = (__ldg(b3) + stencilS<3>(tile, w3, r_o, jp, d2, rr0)) * scale;
        float v2 = (__ldg(b6) + stencilS<6>(tile, w6, r_o, jp, d2, rr0)) * scale;
        float v3 = (__ldg(b9) + stencilS<9>(tile, w9, r_o, jp, d2, rr0)) * scale;

        sbuf[0 * 576 + d2 * 9 + l2i] = v0;
        sbuf[1 * 576 + d2 * 9 + l2i] = v1;
        sbuf[2 * 576 + d2 * 9 + l2i] = v2;
        sbuf[3 * 576 + d2 * 9 + l2i] = v3;
        __syncthreads();

        int l2base = (bx4 * 4 + rr0) * 8;
        // stores: d fastest -> coalesced 128B rows of the [l][d] layout
#pragma unroll
        for (int i = 0; i < 4; i++) {
            int idx = i * 512 + t;
            int dd  = idx & 63;
            int l   = (idx >> 6) & 7;
            int p   = idx >> 9;
            float v = sbuf[p * 576 + dd * 9 + l];
            __nv_bfloat16 hiv = __float2bfloat16(v);
            __nv_bfloat16 lov = __float2bfloat16(v - __bfloat162float(hiv));
            size_t a = ((size_t)(bh * 4 + p) * 1024 + l2base + l) * 64 + dd;
            Phi[a] = hiv;
            Plo[a] = lov;
        }
        if (rr0 < 3) __syncthreads();
    }
}

// ---------------------------------------------------------------------------
// HMMA bf16 m16n8k16 (classic mma.sync — compiles at compute_103).
// ---------------------------------------------------------------------------
__device__ __forceinline__ void mma16816(float* d,
                                         uint32_t a0, uint32_t a1,
                                         uint32_t a2, uint32_t a3,
                                         uint32_t b0, uint32_t b1) {
    asm volatile(
        "mma.sync.aligned.m16n8k16.row.col.f32.bf16.bf16.f32 "
        "{%0,%1,%2,%3}, {%4,%5,%6,%7}, {%8,%9}, {%0,%1,%2,%3};"
        : "+f"(d[0]), "+f"(d[1]), "+f"(d[2]), "+f"(d[3])
        : "r"(a0), "r"(a1), "r"(a2), "r"(a3), "r"(b0), "r"(b1));
}

__device__ __forceinline__ void smax4(float a0, float a1, float a2, float a3,
                                      float* al0, float* al1, float* al2, float* al3) {
    float m  = fmaxf(fmaxf(a0, a1), fmaxf(a2, a3));
    float d0 = a0 - m, d1 = a1 - m, d2 = a2 - m, d3 = a3 - m;
    const float TH = -87.f;
    int cnt = (d0 > TH) + (d1 > TH) + (d2 > TH) + (d3 > TH);
    if (cnt == 1) {   // one-hot (reference exp underflows to exactly this)
        *al0 += (d0 == 0.f) ? 1.f : 0.f;
        *al1 += (d1 == 0.f) ? 1.f : 0.f;
        *al2 += (d2 == 0.f) ? 1.f : 0.f;
        *al3 += (d3 == 0.f) ? 1.f : 0.f;
    } else {
        float e0 = __expf(d0), e1 = __expf(d1), e2 = __expf(d2), e3 = __expf(d3);
        float inv = 1.f / (e0 + e1 + e2 + e3);
        *al0 += e0 * inv; *al1 += e1 * inv; *al2 += e2 * inv; *al3 += e3 * inv;
    }
}

// ---------------------------------------------------------------------------
// Fused attention via HMMA: scores = Qhi·Khi + Qhi·Klo + Qlo·Khi (fp32 acc),
// softmax over p thread-locally on D fragments, q-reduction via shfl + smem.
// Grid (16 kt, 32 bh); block 256 = 8 warps; warp covers 8 m-tiles (128 q).
// attn_out written exactly once per (bh,kt) -> no atomics, deterministic.
// ---------------------------------------------------------------------------
__global__ void __launch_bounds__(256, 1) attn_kernel(float* __restrict__ out) {
    __shared__ float red[8][256];
    int t = threadIdx.x, lane = t & 31, w = t >> 5;
    int gr = lane >> 2, tq = lane & 3;
    int kt = blockIdx.x, bh = blockIdx.y;

    const uint32_t* Qh = (const uint32_t*)g_Qhi;  // 1 u32 = 2 bf16 (d-pair)
    const uint32_t* Ql = (const uint32_t*)g_Qlo;
    const uint32_t* Kh = (const uint32_t*)g_Khi;
    const uint32_t* Kl = (const uint32_t*)g_Klo;
    // row stride in u32 units: 64 bf16 = 32 u32
    float al[4][8][2];
#pragma unroll
    for (int p = 0; p < 4; p++)
#pragma unroll
        for (int n = 0; n < 8; n++) { al[p][n][0] = 0.f; al[p][n][1] = 0.f; }

    for (int mt = 0; mt < 8; mt++) {
        int q0 = w * 128 + mt * 16;
#pragma unroll
        for (int ntc = 0; ntc < 2; ntc++) {
            float D[4][4][4];
#pragma unroll
            for (int p = 0; p < 4; p++)
#pragma unroll
                for (int n = 0; n < 4; n++)
#pragma unroll
                    for (int j = 0; j < 4; j++) D[p][n][j] = 0.f;

#pragma unroll
            for (int p = 0; p < 4; p++) {
                size_t qbase = ((size_t)(bh * 4 + p) * 1024 + q0) * 32;
                size_t kbase = ((size_t)(bh * 4 + p) * 1024 + kt * 64 + ntc * 32) * 32;
#pragma unroll
                for (int ks = 0; ks < 4; ks++) {
                    size_t ar0 = qbase + (size_t)gr * 32 + ks * 8 + tq;
                    size_t ar1 = qbase + (size_t)(gr + 8) * 32 + ks * 8 + tq;
                    uint32_t ah0 = __ldg(Qh + ar0);
                    uint32_t ah1 = __ldg(Qh + ar1);
                    uint32_t ah2 = __ldg(Qh + ar0 + 4);
                    uint32_t ah3 = __ldg(Qh + ar1 + 4);
                    uint32_t al0 = __ldg(Ql + ar0);
                    uint32_t al1 = __ldg(Ql + ar1);
                    uint32_t al2 = __ldg(Ql + ar0 + 4);
                    uint32_t al3 = __ldg(Ql + ar1 + 4);
#pragma unroll
                    for (int ntl = 0; ntl < 4; ntl++) {
                        size_t br = kbase + (size_t)(ntl * 8 + gr) * 32 + ks * 8 + tq;
                        uint32_t bh0 = __ldg(Kh + br);
                        uint32_t bh1 = __ldg(Kh + br + 4);
                        uint32_t bl0 = __ldg(Kl + br);
                        uint32_t bl1 = __ldg(Kl + br + 4);
                        mma16816(D[p][ntl], ah0, ah1, ah2, ah3, bh0, bh1);
                        mma16816(D[p][ntl], ah0, ah1, ah2, ah3, bl0, bl1);
                        mma16816(D[p][ntl], al0, al1, al2, al3, bh0, bh1);
                    }
                }
            }
            // softmax over p; rows r and r+8 fold into the same k column
#pragma unroll
            for (int ntl = 0; ntl < 4; ntl++) {
                int nt = ntc * 4 + ntl;
#pragma unroll
                for (int j = 0; j < 2; j++) {
                    smax4(D[0][ntl][j], D[1][ntl][j], D[2][ntl][j], D[3][ntl][j],
                          &al[0][nt][j], &al[1][nt][j], &al[2][nt][j], &al[3][nt][j]);
                    smax4(D[0][ntl][2 + j], D[1][ntl][2 + j], D[2][ntl][2 + j], D[3][ntl][2 + j],
                          &al[0][nt][j], &al[1][nt][j], &al[2][nt][j], &al[3][nt][j]);
                }
            }
        }
    }

    // Reduce over gr (8 rows) via shfl; lanes 0-3 hold per-(tq) sums
#pragma unroll
    for (int p = 0; p < 4; p++)
#pragma unroll
        for (int n = 0; n < 8; n++)
#pragma unroll
            for (int j = 0; j < 2; j++) {
                float v = al[p][n][j];
                v += __shfl_xor_sync(0xffffffffu, v, 4);
                v += __shfl_xor_sync(0xffffffffu, v, 8);
                v += __shfl_xor_sync(0xffffffffu, v, 16);
                if (lane < 4) red[w][p * 64 + n * 8 + tq * 2 + j] = v;
            }
    __syncthreads();
    {
        int p = t >> 6, k = t & 63;
        float s = 0.f;
#pragma unroll
        for (int ww = 0; ww < 8; ww++) s += red[ww][t];
        out[2097152 + (size_t)(bh * 4 + p) * 1024 + kt * 64 + k] = s;
    }
}

// ---------------------------------------------------------------------------
// context[b,h,q,d] = sum_k V[b,h,k,d]  (softmax over p sums to 1 exactly)
// ---------------------------------------------------------------------------
__global__ void context_kernel(const float* __restrict__ V, float* __restrict__ out) {
    __shared__ float part[4][64];
    __shared__ float fin[64];
    int bh = blockIdx.x;
    int t = threadIdx.x;           // 256
    int d = t & 63, pr = t >> 6;
    const float* Vb = V + (size_t)bh * 65536;
    float s = 0.f;
    for (int k = pr * 256; k < pr * 256 + 256; k++) s += Vb[(size_t)k * 64 + d];
    part[pr][d] = s;
    __syncthreads();
    if (t < 64) fin[t] = part[0][t] + part[1][t] + part[2][t] + part[3][t];
    __syncthreads();
    float* ob = out + (size_t)bh * 65536;
#pragma unroll 4
    for (int i = 0; i < 256; i++) {
        int lin = i * 256 + t;
        ob[lin] = fin[lin & 63];
    }
}

// ---------------------------------------------------------------------------
extern "C" void kernel_launch(void* const* d_in, const int* in_sizes, int n_in,
                              void* d_out, int out_size) {
    (void)in_sizes; (void)n_in; (void)out_size;
    const float* Q = (const float*)d_in[0];
    const float* K = (const float*)d_in[1];
    const float* V = (const float*)d_in[2];
    const float* wq1 = (const float*)d_in[3];  const float* bq1 = (const float*)d_in[4];
    const float* wq3 = (const float*)d_in[5];  const float* bq3 = (const float*)d_in[6];
    const float* wq6 = (const float*)d_in[7];  const float* bq6 = (const float*)d_in[8];
    const float* wq9 = (const float*)d_in[9];  const float* bq9 = (const float*)d_in[10];
    const float* wk1 = (const float*)d_in[11]; const float* bk1 = (const float*)d_in[12];
    const float* wk3 = (const float*)d_in[13]; const float* bk3 = (const float*)d_in[14];
    const float* wk6 = (const float*)d_in[15]; const float* bk6 = (const float*)d_in[16];
    const float* wk9 = (const float*)d_in[17]; const float* bk9 = (const float*)d_in[18];
    float* out = (float*)d_out;

    fft512_rows<<<8192, 256>>>(Q, K);
    fft1024_cols<<<1024, 512>>>();

    multiscale<<<dim3(32, 32, 2), 512>>>(wq1, bq1, wq3, bq3, wq6, bq6, wq9, bq9,
                                         wk1, bk1, wk3, bk3, wk6, bk6, wk9, bk9);

    attn_kernel<<<dim3(16, 32), 256>>>(out);   // launch #4 -> profiled

    context_kernel<<<32, 256>>>(V, out);
}

// round 16
// speedup vs baseline: 2.3252x; 2.3252x over previous
#include <cuda_runtime.h>
#include <cuda_bf16.h>
#include <cstdint>

// ---------------------------------------------------------------------------
// Shapes: b=4, h=8, l=1024, d=64. Per-batch flat matrix M: 1024 x 512.
// Outputs: context (4,8,1024,64) then attn_out (4,8,4,1024).
// ---------------------------------------------------------------------------

__device__ float  g_cre[2 * 4 * 1024 * 512];
__device__ float  g_cim[2 * 4 * 1024 * 512];
__device__ float  g_Mq [4 * 1024 * 512];
__device__ float  g_Mk [4 * 1024 * 512];
// Fragment-major bf16 operands for m16n8k16 HMMA:
// QF[pg(128)][qt(64)][ks(4)][lane(32)][8]  (ah0..ah3, al0..al3)
// KF[pg(128)][nt(128)][ks(4)][lane(32)][4] (bh0, bh1, bl0, bl1)
__device__ uint32_t g_QF[128 * 64 * 4 * 32 * 8];
__device__ uint32_t g_KF[128 * 128 * 4 * 32 * 4];

// ---------------------------------------------------------------------------
// Stage 1: 512-pt FFT along each contiguous row (smem twiddle LUT).
// ---------------------------------------------------------------------------
__global__ void fft512_rows(const float* __restrict__ Qin,
                            const float* __restrict__ Kin) {
    __shared__ float re[512], im[512];
    __shared__ float2 tw[512];
    int R = blockIdx.x;                        // 0..8191
    const float* src = (R < 4096) ? Qin : Kin;
    const float* row = src + (size_t)(R & 4095) * 512;
    int t = threadIdx.x;  // 256
    for (int i = t; i < 512; i += 256) {
        re[i] = row[__brev((unsigned)i) >> 23];
        im[i] = 0.f;
        float si, co;
        sincospif(-(float)i / 512.f, &si, &co);
        tw[i] = make_float2(co, si);
    }
    __syncthreads();
    for (int s = 0; s < 9; s++) {
        int hl = 1 << s;
        int pos = t & (hl - 1);
        int i0 = ((t >> s) << (s + 1)) + pos;
        int i1 = i0 + hl;
        float2 w = tw[pos << (9 - s)];
        float xr = re[i1], xi = im[i1];
        float tr = w.x * xr - w.y * xi;
        float ti = w.x * xi + w.y * xr;
        float ur = re[i0], ui = im[i0];
        re[i0] = ur + tr; im[i0] = ui + ti;
        re[i1] = ur - tr; im[i1] = ui - ti;
        __syncthreads();
    }
    float* cr = g_cre + (size_t)R * 512;
    float* ci = g_cim + (size_t)R * 512;
    for (int i = t; i < 512; i += 256) { cr[i] = re[i]; ci[i] = im[i]; }
}

// ---------------------------------------------------------------------------
// Stage 2: 1024-pt FFT along columns, keep real part (smem twiddle LUT).
// ---------------------------------------------------------------------------
__global__ void fft1024_cols() {
    __shared__ float re[4096], im[4096];
    __shared__ float2 tw[512];
    int t = threadIdx.x;                 // 512
    int bi2 = blockIdx.x >> 7;           // 0..7 = which*4 + b
    int j0  = (blockIdx.x & 127) << 2;
    size_t gb = (size_t)bi2 << 19;
    {
        float si, co;
        sincospif(-(float)t / 512.f, &si, &co);
        tw[t] = make_float2(co, si);
    }
    for (int idx = t; idx < 4096; idx += 512) {
        int r = idx >> 2, c = idx & 3;
        int rv = __brev((unsigned)r) >> 22;
        size_t a = gb + (size_t)rv * 512 + j0 + c;
        re[idx] = g_cre[a];
        im[idx] = g_cim[a];
    }
    __syncthreads();
    for (int s = 0; s < 10; s++) {
        for (int u = t; u < 2048; u += 512) {
            int c = u & 3, jb = u >> 2;
            int hl = 1 << s;
            int pos = jb & (hl - 1);
            int i0 = ((jb >> s) << (s + 1)) + pos;
            int i1 = i0 + hl;
            float2 w = tw[pos << (9 - s)];
            int a0 = (i0 << 2) + c, a1 = (i1 << 2) + c;
            float xr = re[a1], xi = im[a1];
            float tr = w.x * xr - w.y * xi;
            float ti = w.x * xi + w.y * xr;
            float ur = re[a0], ui = im[a0];
            re[a0] = ur + tr; im[a0] = ui + ti;
            re[a1] = ur - tr; im[a1] = ui - ti;
        }
        __syncthreads();
    }
    float* M = (bi2 >= 4) ? g_Mk : g_Mq;
    size_t mb = (size_t)(bi2 & 3) << 19;
    for (int idx = t; idx < 4096; idx += 512) {
        int r = idx >> 2, c = idx & 3;
        M[mb + (size_t)r * 512 + j0 + c] = re[idx];
    }
}

// ---------------------------------------------------------------------------
// Multi-scale stencil, smem-staged, 4 r_o per block. Emits bf16 hi/lo split
// DIRECTLY in HMMA fragment-major order (QF / KF).
// Fragment algebra (1:1 with R15's verified loads):
//   Q: qt=l2>>4, r16=l2&15, gr=r16&7, hi8=r16>>3; dpair=ks*8+rem,
//      tq=rem&3, second=rem>>2; lane=gr*4+tq; slot=hi8+2*second (lo at +4).
//   K: nt=l2>>3, gr=l2&7; slot=second (b0/b1), lo at +2.
// ---------------------------------------------------------------------------
template <int C>
__device__ __forceinline__ float stencilS(const float* __restrict__ tile,
                                          const float* __restrict__ w,
                                          int r_o, int jp, int d2, int rr0) {
    float acc = 0.f;
#pragma unroll
    for (int ci = 0; ci < C; ci++) {
        int tt  = 64 * ci + d2;
        int il  = 9 - C + (tt % C);
        int col = jp + (tt / C) - C;
        if ((r_o - 9 + il) >= 0 && col >= 0)
            acc = fmaf(__ldg(w + ci), tile[(rr0 + il) * 513 + col], acc);
    }
    return acc;
}

__device__ __forceinline__ uint32_t pack_bf16x2(float a, float b) {
    __nv_bfloat162 h = __floats2bfloat162_rn(a, b);
    return *(uint32_t*)&h;
}

__global__ void __launch_bounds__(512) multiscale(
    const float* __restrict__ wq1, const float* __restrict__ bq1,
    const float* __restrict__ wq3, const float* __restrict__ bq3,
    const float* __restrict__ wq6, const float* __restrict__ bq6,
    const float* __restrict__ wq9, const float* __restrict__ bq9,
    const float* __restrict__ wk1, const float* __restrict__ bk1,
    const float* __restrict__ wk3, const float* __restrict__ bk3,
    const float* __restrict__ wk6, const float* __restrict__ bk6,
    const float* __restrict__ wk9, const float* __restrict__ bk9) {
    __shared__ float tile[12 * 513];
    __shared__ float sbuf[4 * 64 * 9];
    int t   = threadIdx.x;
    int d2  = t & 63;
    int l2i = (t >> 6) & 7;
    int bx4 = blockIdx.x;                      // 0..31
    int bh  = blockIdx.y;
    int which = blockIdx.z;
    int b = bh >> 3, hi = bh & 7;

    const float* M = which ? g_Mk : g_Mq;
    const float* w1 = which ? wk1 : wq1;  const float* b1 = which ? bk1 : bq1;
    const float* w3 = which ? wk3 : wq3;  const float* b3 = which ? bk3 : bq3;
    const float* w6 = which ? wk6 : wq6;  const float* b6 = which ? bk6 : bq6;
    const float* w9 = which ? wk9 : wq9;  const float* b9 = which ? bk9 : bq9;
    float scale = which ? 1.0f : 0.125f;

    const float* Mb = M + ((size_t)b << 19);
    int r_o0 = (hi << 7) + bx4 * 4;
    int jp   = l2i << 6;

    for (int i = t; i < 12 * 512; i += 512) {
        int rr = i >> 9, cc = i & 511;
        int grow = r_o0 - 9 + rr;
        tile[rr * 513 + cc] = (grow >= 0) ? __ldg(Mb + grow * 512 + cc) : 0.f;
    }
    __syncthreads();

#pragma unroll
    for (int rr0 = 0; rr0 < 4; rr0++) {
        int r_o = r_o0 + rr0;
        float v0 = (__ldg(b1) + stencilS<1>(tile, w1, r_o, jp, d2, rr0)) * scale;
        float v1 = (__ldg(b3) + stencilS<3>(tile, w3, r_o, jp, d2, rr0)) * scale;
        float v2 = (__ldg(b6) + stencilS<6>(tile, w6, r_o, jp, d2, rr0)) * scale;
        float v3 = (__ldg(b9) + stencilS<9>(tile, w9, r_o, jp, d2, rr0)) * scale;

        sbuf[0 * 576 + d2 * 9 + l2i] = v0;
        sbuf[1 * 576 + d2 * 9 + l2i] = v1;
        sbuf[2 * 576 + d2 * 9 + l2i] = v2;
        sbuf[3 * 576 + d2 * 9 + l2i] = v3;
        __syncthreads();

        // Fragment-major store: 2 iterations x 512 threads = 1024 (p,l2,dpair)
#pragma unroll
        for (int i = 0; i < 2; i++) {
            int idx = i * 512 + t;
            int dpair = idx & 31;
            int li    = (idx >> 5) & 7;
            int p     = idx >> 8;
            float va = sbuf[p * 576 + (dpair * 2 + 0) * 9 + li];
            float vb = sbuf[p * 576 + (dpair * 2 + 1) * 9 + li];
            __nv_bfloat16 ha = __float2bfloat16(va);
            __nv_bfloat16 hb = __float2bfloat16(vb);
            float ra = va - __bfloat162float(ha);
            float rb = vb - __bfloat162float(hb);
            uint32_t hiw; { __nv_bfloat162 h2 = {ha, hb}; hiw = *(uint32_t*)&h2; }
            uint32_t low = pack_bf16x2(ra, rb);

            int l2g = (bx4 * 4 + rr0) * 8 + li;
            int pg  = bh * 4 + p;
            int ks = dpair >> 3, rem = dpair & 7;
            int tq = rem & 3, second = rem >> 2;
            if (which == 0) {
                int qt = l2g >> 4, r16 = l2g & 15;
                int gr = r16 & 7, hi8 = r16 >> 3;
                int lane = gr * 4 + tq;
                int slot = hi8 + second * 2;
                size_t base = ((((size_t)pg * 64 + qt) * 4 + ks) * 32 + lane) * 8;
                g_QF[base + slot]     = hiw;
                g_QF[base + slot + 4] = low;
            } else {
                int nt = l2g >> 3, gr = l2g & 7;
                int lane = gr * 4 + tq;
                size_t base = ((((size_t)pg * 128 + nt) * 4 + ks) * 32 + lane) * 4;
                g_KF[base + second]     = hiw;
                g_KF[base + second + 2] = low;
            }
        }
        if (rr0 < 3) __syncthreads();
    }
}

// ---------------------------------------------------------------------------
// HMMA bf16 m16n8k16 (classic mma.sync — compiles at compute_103).
// ---------------------------------------------------------------------------
__device__ __forceinline__ void mma16816(float* d,
                                         uint32_t a0, uint32_t a1,
                                         uint32_t a2, uint32_t a3,
                                         uint32_t b0, uint32_t b1) {
    asm volatile(
        "mma.sync.aligned.m16n8k16.row.col.f32.bf16.bf16.f32 "
        "{%0,%1,%2,%3}, {%4,%5,%6,%7}, {%8,%9}, {%0,%1,%2,%3};"
        : "+f"(d[0]), "+f"(d[1]), "+f"(d[2]), "+f"(d[3])
        : "r"(a0), "r"(a1), "r"(a2), "r"(a3), "r"(b0), "r"(b1));
}

__device__ __forceinline__ void smax4(float a0, float a1, float a2, float a3,
                                      float* al0, float* al1, float* al2, float* al3) {
    float m  = fmaxf(fmaxf(a0, a1), fmaxf(a2, a3));
    float d0 = a0 - m, d1 = a1 - m, d2 = a2 - m, d3 = a3 - m;
    const float TH = -87.f;
    int cnt = (d0 > TH) + (d1 > TH) + (d2 > TH) + (d3 > TH);
    if (cnt == 1) {   // one-hot (reference exp underflows to exactly this)
        *al0 += (d0 == 0.f) ? 1.f : 0.f;
        *al1 += (d1 == 0.f) ? 1.f : 0.f;
        *al2 += (d2 == 0.f) ? 1.f : 0.f;
        *al3 += (d3 == 0.f) ? 1.f : 0.f;
    } else {
        float e0 = __expf(d0), e1 = __expf(d1), e2 = __expf(d2), e3 = __expf(d3);
        float inv = 1.f / (e0 + e1 + e2 + e3);
        *al0 += e0 * inv; *al1 += e1 * inv; *al2 += e2 * inv; *al3 += e3 * inv;
    }
}

// ---------------------------------------------------------------------------
// Fused attention via HMMA with fragment-major operands: every A fragment is
// 2 coalesced LDG.128; every B fragment is 1 LDG.128 (L1-resident across mt).
// Grid (16 kt, 32 bh); block 256 = 8 warps; warp covers 8 m-tiles (128 q).
// attn_out written exactly once per (bh,kt) -> no atomics, deterministic.
// ---------------------------------------------------------------------------
__global__ void __launch_bounds__(256, 1) attn_kernel(float* __restrict__ out) {
    __shared__ float red[8][256];
    int t = threadIdx.x, lane = t & 31, w = t >> 5;
    int tq = lane & 3;
    int kt = blockIdx.x, bh = blockIdx.y;

    float al[4][8][2];
#pragma unroll
    for (int p = 0; p < 4; p++)
#pragma unroll
        for (int n = 0; n < 8; n++) { al[p][n][0] = 0.f; al[p][n][1] = 0.f; }

    for (int mt = 0; mt < 8; mt++) {
        int qt = w * 8 + mt;
#pragma unroll
        for (int ntc = 0; ntc < 2; ntc++) {
            float D[4][4][4];
#pragma unroll
            for (int p = 0; p < 4; p++)
#pragma unroll
                for (int n = 0; n < 4; n++)
#pragma unroll
                    for (int j = 0; j < 4; j++) D[p][n][j] = 0.f;

#pragma unroll
            for (int p = 0; p < 4; p++) {
                int pg = bh * 4 + p;
#pragma unroll
                for (int ks = 0; ks < 4; ks++) {
                    size_t aoff = ((((size_t)pg * 64 + qt) * 4 + ks) * 32 + lane) * 8;
                    uint4 AH = __ldg((const uint4*)(g_QF + aoff));
                    uint4 AL = __ldg((const uint4*)(g_QF + aoff + 4));
#pragma unroll
                    for (int ntl = 0; ntl < 4; ntl++) {
                        int ntg = kt * 8 + ntc * 4 + ntl;
                        size_t boff = ((((size_t)pg * 128 + ntg) * 4 + ks) * 32 + lane) * 4;
                        uint4 B = __ldg((const uint4*)(g_KF + boff));
                        mma16816(D[p][ntl], AH.x, AH.y, AH.z, AH.w, B.x, B.y);
                        mma16816(D[p][ntl], AH.x, AH.y, AH.z, AH.w, B.z, B.w);
                        mma16816(D[p][ntl], AL.x, AL.y, AL.z, AL.w, B.x, B.y);
                    }
                }
            }
            // softmax over p; rows r and r+8 fold into the same k column
#pragma unroll
            for (int ntl = 0; ntl < 4; ntl++) {
                int nt = ntc * 4 + ntl;
#pragma unroll
                for (int j = 0; j < 2; j++) {
                    smax4(D[0][ntl][j], D[1][ntl][j], D[2][ntl][j], D[3][ntl][j],
                          &al[0][nt][j], &al[1][nt][j], &al[2][nt][j], &al[3][nt][j]);
                    smax4(D[0][ntl][2 + j], D[1][ntl][2 + j], D[2][ntl][2 + j], D[3][ntl][2 + j],
                          &al[0][nt][j], &al[1][nt][j], &al[2][nt][j], &al[3][nt][j]);
                }
            }
        }
    }

    // Reduce over gr (8 rows) via shfl; lanes 0-3 hold per-(tq) sums
#pragma unroll
    for (int p = 0; p < 4; p++)
#pragma unroll
        for (int n = 0; n < 8; n++)
#pragma unroll
            for (int j = 0; j < 2; j++) {
                float v = al[p][n][j];
                v += __shfl_xor_sync(0xffffffffu, v, 4);
                v += __shfl_xor_sync(0xffffffffu, v, 8);
                v += __shfl_xor_sync(0xffffffffu, v, 16);
                if (lane < 4) red[w][p * 64 + n * 8 + tq * 2 + j] = v;
            }
    __syncthreads();
    {
        int p = t >> 6, k = t & 63;
        float s = 0.f;
#pragma unroll
        for (int ww = 0; ww < 8; ww++) s += red[ww][t];
        out[2097152 + (size_t)(bh * 4 + p) * 1024 + kt * 64 + k] = s;
    }
}

// ---------------------------------------------------------------------------
// context[b,h,q,d] = sum_k V[b,h,k,d]  (softmax over p sums to 1 exactly)
// ---------------------------------------------------------------------------
__global__ void context_kernel(const float* __restrict__ V, float* __restrict__ out) {
    __shared__ float part[4][64];
    __shared__ float fin[64];
    int bh = blockIdx.x;
    int t = threadIdx.x;           // 256
    int d = t & 63, pr = t >> 6;
    const float* Vb = V + (size_t)bh * 65536;
    float s = 0.f;
    for (int k = pr * 256; k < pr * 256 + 256; k++) s += Vb[(size_t)k * 64 + d];
    part[pr][d] = s;
    __syncthreads();
    if (t < 64) fin[t] = part[0][t] + part[1][t] + part[2][t] + part[3][t];
    __syncthreads();
    float* ob = out + (size_t)bh * 65536;
#pragma unroll 4
    for (int i = 0; i < 256; i++) {
        int lin = i * 256 + t;
        ob[lin] = fin[lin & 63];
    }
}

// ---------------------------------------------------------------------------
extern "C" void kernel_launch(void* const* d_in, const int* in_sizes, int n_in,
                              void* d_out, int out_size) {
    (void)in_sizes; (void)n_in; (void)out_size;
    const float* Q = (const float*)d_in[0];
    const float* K = (const float*)d_in[1];
    const float* V = (const float*)d_in[2];
    const float* wq1 = (const float*)d_in[3];  const float* bq1 = (const float*)d_in[4];
    const float* wq3 = (const float*)d_in[5];  const float* bq3 = (const float*)d_in[6];
    const float* wq6 = (const float*)d_in[7];  const float* bq6 = (const float*)d_in[8];
    const float* wq9 = (const float*)d_in[9];  const float* bq9 = (const float*)d_in[10];
    const float* wk1 = (const float*)d_in[11]; const float* bk1 = (const float*)d_in[12];
    const float* wk3 = (const float*)d_in[13]; const float* bk3 = (const float*)d_in[14];
    const float* wk6 = (const float*)d_in[15]; const float* bk6 = (const float*)d_in[16];
    const float* wk9 = (const float*)d_in[17]; const float* bk9 = (const float*)d_in[18];
    float* out = (float*)d_out;

    fft512_rows<<<8192, 256>>>(Q, K);
    fft1024_cols<<<1024, 512>>>();

    multiscale<<<dim3(32, 32, 2), 512>>>(wq1, bq1, wq3, bq3, wq6, bq6, wq9, bq9,
                                         wk1, bk1, wk3, bk3, wk6, bk6, wk9, bk9);

    attn_kernel<<<dim3(16, 32), 256>>>(out);   // launch #4 -> profiled

    context_kernel<<<32, 256>>>(V, out);
}

// round 17
// speedup vs baseline: 2.3622x; 1.0159x over previous
#include <cuda_runtime.h>
#include <cuda_bf16.h>
#include <cstdint>

// ---------------------------------------------------------------------------
// Shapes: b=4, h=8, l=1024, d=64. Per-batch flat matrix M: 1024 x 512.
// Outputs: context (4,8,1024,64) then attn_out (4,8,4,1024).
// ---------------------------------------------------------------------------

__device__ float  g_cre[2 * 4 * 1024 * 512];
__device__ float  g_cim[2 * 4 * 1024 * 512];
__device__ float  g_Mq [4 * 1024 * 512];
__device__ float  g_Mk [4 * 1024 * 512];
// Fragment-major bf16 operands for m16n8k16 HMMA:
// QF[pg(128)][qt(64)][ks(4)][lane(32)][8]  (ah0..ah3, al0..al3)
// KF[pg(128)][nt(128)][ks(4)][lane(32)][4] (bh0, bh1, bl0, bl1)
__device__ uint32_t g_QF[128 * 64 * 4 * 32 * 8];
__device__ uint32_t g_KF[128 * 128 * 4 * 32 * 4];

// ---------------------------------------------------------------------------
// Stage 1: 512-pt FFT along each contiguous row (smem twiddle LUT).
// ---------------------------------------------------------------------------
__global__ void fft512_rows(const float* __restrict__ Qin,
                            const float* __restrict__ Kin) {
    __shared__ float re[512], im[512];
    __shared__ float2 tw[512];
    int R = blockIdx.x;                        // 0..8191
    const float* src = (R < 4096) ? Qin : Kin;
    const float* row = src + (size_t)(R & 4095) * 512;
    int t = threadIdx.x;  // 256
    for (int i = t; i < 512; i += 256) {
        re[i] = row[__brev((unsigned)i) >> 23];
        im[i] = 0.f;
        float si, co;
        sincospif(-(float)i / 512.f, &si, &co);
        tw[i] = make_float2(co, si);
    }
    __syncthreads();
    for (int s = 0; s < 9; s++) {
        int hl = 1 << s;
        int pos = t & (hl - 1);
        int i0 = ((t >> s) << (s + 1)) + pos;
        int i1 = i0 + hl;
        float2 w = tw[pos << (9 - s)];
        float xr = re[i1], xi = im[i1];
        float tr = w.x * xr - w.y * xi;
        float ti = w.x * xi + w.y * xr;
        float ur = re[i0], ui = im[i0];
        re[i0] = ur + tr; im[i0] = ui + ti;
        re[i1] = ur - tr; im[i1] = ui - ti;
        __syncthreads();
    }
    float* cr = g_cre + (size_t)R * 512;
    float* ci = g_cim + (size_t)R * 512;
    for (int i = t; i < 512; i += 256) { cr[i] = re[i]; ci[i] = im[i]; }
}

// ---------------------------------------------------------------------------
// Stage 2: 1024-pt FFT along columns, keep real part (smem twiddle LUT).
// ---------------------------------------------------------------------------
__global__ void fft1024_cols() {
    __shared__ float re[4096], im[4096];
    __shared__ float2 tw[512];
    int t = threadIdx.x;                 // 512
    int bi2 = blockIdx.x >> 7;           // 0..7 = which*4 + b
    int j0  = (blockIdx.x & 127) << 2;
    size_t gb = (size_t)bi2 << 19;
    {
        float si, co;
        sincospif(-(float)t / 512.f, &si, &co);
        tw[t] = make_float2(co, si);
    }
    for (int idx = t; idx < 4096; idx += 512) {
        int r = idx >> 2, c = idx & 3;
        int rv = __brev((unsigned)r) >> 22;
        size_t a = gb + (size_t)rv * 512 + j0 + c;
        re[idx] = g_cre[a];
        im[idx] = g_cim[a];
    }
    __syncthreads();
    for (int s = 0; s < 10; s++) {
        for (int u = t; u < 2048; u += 512) {
            int c = u & 3, jb = u >> 2;
            int hl = 1 << s;
            int pos = jb & (hl - 1);
            int i0 = ((jb >> s) << (s + 1)) + pos;
            int i1 = i0 + hl;
            float2 w = tw[pos << (9 - s)];
            int a0 = (i0 << 2) + c, a1 = (i1 << 2) + c;
            float xr = re[a1], xi = im[a1];
            float tr = w.x * xr - w.y * xi;
            float ti = w.x * xi + w.y * xr;
            float ur = re[a0], ui = im[a0];
            re[a0] = ur + tr; im[a0] = ui + ti;
            re[a1] = ur - tr; im[a1] = ui - ti;
        }
        __syncthreads();
    }
    float* M = (bi2 >= 4) ? g_Mk : g_Mq;
    size_t mb = (size_t)(bi2 & 3) << 19;
    for (int idx = t; idx < 4096; idx += 512) {
        int r = idx >> 2, c = idx & 3;
        M[mb + (size_t)r * 512 + j0 + c] = re[idx];
    }
}

// ---------------------------------------------------------------------------
// Multi-scale stencil, smem-staged, 4 r_o per block. Emits bf16 hi/lo split
// DIRECTLY in HMMA fragment-major order (QF / KF).
// ---------------------------------------------------------------------------
template <int C>
__device__ __forceinline__ float stencilS(const float* __restrict__ tile,
                                          const float* __restrict__ w,
                                          int r_o, int jp, int d2, int rr0) {
    float acc = 0.f;
#pragma unroll
    for (int ci = 0; ci < C; ci++) {
        int tt  = 64 * ci + d2;
        int il  = 9 - C + (tt % C);
        int col = jp + (tt / C) - C;
        if ((r_o - 9 + il) >= 0 && col >= 0)
            acc = fmaf(__ldg(w + ci), tile[(rr0 + il) * 513 + col], acc);
    }
    return acc;
}

__device__ __forceinline__ uint32_t pack_bf16x2(float a, float b) {
    __nv_bfloat162 h = __floats2bfloat162_rn(a, b);
    return *(uint32_t*)&h;
}

__global__ void __launch_bounds__(512) multiscale(
    const float* __restrict__ wq1, const float* __restrict__ bq1,
    const float* __restrict__ wq3, const float* __restrict__ bq3,
    const float* __restrict__ wq6, const float* __restrict__ bq6,
    const float* __restrict__ wq9, const float* __restrict__ bq9,
    const float* __restrict__ wk1, const float* __restrict__ bk1,
    const float* __restrict__ wk3, const float* __restrict__ bk3,
    const float* __restrict__ wk6, const float* __restrict__ bk6,
    const float* __restrict__ wk9, const float* __restrict__ bk9) {
    __shared__ float tile[12 * 513];
    __shared__ float sbuf[4 * 64 * 9];
    int t   = threadIdx.x;
    int d2  = t & 63;
    int l2i = (t >> 6) & 7;
    int bx4 = blockIdx.x;                      // 0..31
    int bh  = blockIdx.y;
    int which = blockIdx.z;
    int b = bh >> 3, hi = bh & 7;

    const float* M = which ? g_Mk : g_Mq;
    const float* w1 = which ? wk1 : wq1;  const float* b1 = which ? bk1 : bq1;
    const float* w3 = which ? wk3 : wq3;  const float* b3 = which ? bk3 : bq3;
    const float* w6 = which ? wk6 : wq6;  const float* b6 = which ? bk6 : bq6;
    const float* w9 = which ? wk9 : wq9;  const float* b9 = which ? bk9 : bq9;
    float scale = which ? 1.0f : 0.125f;

    const float* Mb = M + ((size_t)b << 19);
    int r_o0 = (hi << 7) + bx4 * 4;
    int jp   = l2i << 6;

    for (int i = t; i < 12 * 512; i += 512) {
        int rr = i >> 9, cc = i & 511;
        int grow = r_o0 - 9 + rr;
        tile[rr * 513 + cc] = (grow >= 0) ? __ldg(Mb + grow * 512 + cc) : 0.f;
    }
    __syncthreads();

#pragma unroll
    for (int rr0 = 0; rr0 < 4; rr0++) {
        int r_o = r_o0 + rr0;
        float v0 = (__ldg(b1) + stencilS<1>(tile, w1, r_o, jp, d2, rr0)) * scale;
        float v1 = (__ldg(b3) + stencilS<3>(tile, w3, r_o, jp, d2, rr0)) * scale;
        float v2 = (__ldg(b6) + stencilS<6>(tile, w6, r_o, jp, d2, rr0)) * scale;
        float v3 = (__ldg(b9) + stencilS<9>(tile, w9, r_o, jp, d2, rr0)) * scale;

        sbuf[0 * 576 + d2 * 9 + l2i] = v0;
        sbuf[1 * 576 + d2 * 9 + l2i] = v1;
        sbuf[2 * 576 + d2 * 9 + l2i] = v2;
        sbuf[3 * 576 + d2 * 9 + l2i] = v3;
        __syncthreads();

        // Fragment-major store: 2 iterations x 512 threads = 1024 (p,l2,dpair)
#pragma unroll
        for (int i = 0; i < 2; i++) {
            int idx = i * 512 + t;
            int dpair = idx & 31;
            int li    = (idx >> 5) & 7;
            int p     = idx >> 8;
            float va = sbuf[p * 576 + (dpair * 2 + 0) * 9 + li];
            float vb = sbuf[p * 576 + (dpair * 2 + 1) * 9 + li];
            __nv_bfloat16 ha = __float2bfloat16(va);
            __nv_bfloat16 hb = __float2bfloat16(vb);
            float ra = va - __bfloat162float(ha);
            float rb = vb - __bfloat162float(hb);
            uint32_t hiw; { __nv_bfloat162 h2 = {ha, hb}; hiw = *(uint32_t*)&h2; }
            uint32_t low = pack_bf16x2(ra, rb);

            int l2g = (bx4 * 4 + rr0) * 8 + li;
            int pg  = bh * 4 + p;
            int ks = dpair >> 3, rem = dpair & 7;
            int tq = rem & 3, second = rem >> 2;
            if (which == 0) {
                int qt = l2g >> 4, r16 = l2g & 15;
                int gr = r16 & 7, hi8 = r16 >> 3;
                int lane = gr * 4 + tq;
                int slot = hi8 + second * 2;
                size_t base = ((((size_t)pg * 64 + qt) * 4 + ks) * 32 + lane) * 8;
                g_QF[base + slot]     = hiw;
                g_QF[base + slot + 4] = low;
            } else {
                int nt = l2g >> 3, gr = l2g & 7;
                int lane = gr * 4 + tq;
                size_t base = ((((size_t)pg * 128 + nt) * 4 + ks) * 32 + lane) * 4;
                g_KF[base + second]     = hiw;
                g_KF[base + second + 2] = low;
            }
        }
        if (rr0 < 3) __syncthreads();
    }
}

// ---------------------------------------------------------------------------
// HMMA bf16 m16n8k16 (classic mma.sync — compiles at compute_103).
// ---------------------------------------------------------------------------
__device__ __forceinline__ void mma16816(float* d,
                                         uint32_t a0, uint32_t a1,
                                         uint32_t a2, uint32_t a3,
                                         uint32_t b0, uint32_t b1) {
    asm volatile(
        "mma.sync.aligned.m16n8k16.row.col.f32.bf16.bf16.f32 "
        "{%0,%1,%2,%3}, {%4,%5,%6,%7}, {%8,%9}, {%0,%1,%2,%3};"
        : "+f"(d[0]), "+f"(d[1]), "+f"(d[2]), "+f"(d[3])
        : "r"(a0), "r"(a1), "r"(a2), "r"(a3), "r"(b0), "r"(b1));
}

__device__ __forceinline__ void smax4(float a0, float a1, float a2, float a3,
                                      float* al0, float* al1, float* al2, float* al3) {
    float m  = fmaxf(fmaxf(a0, a1), fmaxf(a2, a3));
    float d0 = a0 - m, d1 = a1 - m, d2 = a2 - m, d3 = a3 - m;
    const float TH = -87.f;
    int cnt = (d0 > TH) + (d1 > TH) + (d2 > TH) + (d3 > TH);
    if (cnt == 1) {   // one-hot (reference exp underflows to exactly this)
        *al0 += (d0 == 0.f) ? 1.f : 0.f;
        *al1 += (d1 == 0.f) ? 1.f : 0.f;
        *al2 += (d2 == 0.f) ? 1.f : 0.f;
        *al3 += (d3 == 0.f) ? 1.f : 0.f;
    } else {
        float e0 = __expf(d0), e1 = __expf(d1), e2 = __expf(d2), e3 = __expf(d3);
        float inv = 1.f / (e0 + e1 + e2 + e3);
        *al0 += e0 * inv; *al1 += e1 * inv; *al2 += e2 * inv; *al3 += e3 * inv;
    }
}

// ---------------------------------------------------------------------------
// Fused attention via HMMA, n-split for occupancy: grid (16 kt, 32 bh, 2 nh);
// each block covers 32 k-columns (4 n-tiles). acc: al[4][4][2] + D[4][2][4]
// = 64 regs -> 2 CTAs/SM (4 warps/SMSP). attn_out written once per block.
// ---------------------------------------------------------------------------
__global__ void __launch_bounds__(256, 2) attn_kernel(float* __restrict__ out) {
    __shared__ float red[8][128];
    int t = threadIdx.x, lane = t & 31, w = t >> 5;
    int tq = lane & 3;
    int kt = blockIdx.x, bh = blockIdx.y, nh = blockIdx.z;

    float al[4][4][2];
#pragma unroll
    for (int p = 0; p < 4; p++)
#pragma unroll
        for (int n = 0; n < 4; n++) { al[p][n][0] = 0.f; al[p][n][1] = 0.f; }

    for (int mt = 0; mt < 8; mt++) {
        int qt = w * 8 + mt;
#pragma unroll
        for (int ntc = 0; ntc < 2; ntc++) {
            float D[4][2][4];
#pragma unroll
            for (int p = 0; p < 4; p++)
#pragma unroll
                for (int n = 0; n < 2; n++)
#pragma unroll
                    for (int j = 0; j < 4; j++) D[p][n][j] = 0.f;

#pragma unroll
            for (int p = 0; p < 4; p++) {
                int pg = bh * 4 + p;
#pragma unroll
                for (int ks = 0; ks < 4; ks++) {
                    size_t aoff = ((((size_t)pg * 64 + qt) * 4 + ks) * 32 + lane) * 8;
                    uint4 AH = __ldg((const uint4*)(g_QF + aoff));
                    uint4 AL = __ldg((const uint4*)(g_QF + aoff + 4));
#pragma unroll
                    for (int ntl = 0; ntl < 2; ntl++) {
                        int ntg = kt * 8 + nh * 4 + ntc * 2 + ntl;
                        size_t boff = ((((size_t)pg * 128 + ntg) * 4 + ks) * 32 + lane) * 4;
                        uint4 B = __ldg((const uint4*)(g_KF + boff));
                        mma16816(D[p][ntl], AH.x, AH.y, AH.z, AH.w, B.x, B.y);
                        mma16816(D[p][ntl], AH.x, AH.y, AH.z, AH.w, B.z, B.w);
                        mma16816(D[p][ntl], AL.x, AL.y, AL.z, AL.w, B.x, B.y);
                    }
                }
            }
            // softmax over p; rows r and r+8 fold into the same k column
#pragma unroll
            for (int ntl = 0; ntl < 2; ntl++) {
                int nt = ntc * 2 + ntl;
#pragma unroll
                for (int j = 0; j < 2; j++) {
                    smax4(D[0][ntl][j], D[1][ntl][j], D[2][ntl][j], D[3][ntl][j],
                          &al[0][nt][j], &al[1][nt][j], &al[2][nt][j], &al[3][nt][j]);
                    smax4(D[0][ntl][2 + j], D[1][ntl][2 + j], D[2][ntl][2 + j], D[3][ntl][2 + j],
                          &al[0][nt][j], &al[1][nt][j], &al[2][nt][j], &al[3][nt][j]);
                }
            }
        }
    }

    // Reduce over gr (8 rows) via shfl; lanes 0-3 hold per-(tq) sums
#pragma unroll
    for (int p = 0; p < 4; p++)
#pragma unroll
        for (int n = 0; n < 4; n++)
#pragma unroll
            for (int j = 0; j < 2; j++) {
                float v = al[p][n][j];
                v += __shfl_xor_sync(0xffffffffu, v, 4);
                v += __shfl_xor_sync(0xffffffffu, v, 8);
                v += __shfl_xor_sync(0xffffffffu, v, 16);
                if (lane < 4) red[w][p * 32 + n * 8 + tq * 2 + j] = v;
            }
    __syncthreads();
    if (t < 128) {
        int p = t >> 5, k = t & 31;
        float s = 0.f;
#pragma unroll
        for (int ww = 0; ww < 8; ww++) s += red[ww][t];
        out[2097152 + (size_t)(bh * 4 + p) * 1024 + kt * 64 + nh * 32 + k] = s;
    }
}

// ---------------------------------------------------------------------------
// context[b,h,q,d] = sum_k V[b,h,k,d]  (softmax over p sums to 1 exactly)
// ---------------------------------------------------------------------------
__global__ void context_kernel(const float* __restrict__ V, float* __restrict__ out) {
    __shared__ float part[4][64];
    __shared__ float fin[64];
    int bh = blockIdx.x;
    int t = threadIdx.x;           // 256
    int d = t & 63, pr = t >> 6;
    const float* Vb = V + (size_t)bh * 65536;
    float s = 0.f;
    for (int k = pr * 256; k < pr * 256 + 256; k++) s += Vb[(size_t)k * 64 + d];
    part[pr][d] = s;
    __syncthreads();
    if (t < 64) fin[t] = part[0][t] + part[1][t] + part[2][t] + part[3][t];
    __syncthreads();
    float* ob = out + (size_t)bh * 65536;
#pragma unroll 4
    for (int i = 0; i < 256; i++) {
        int lin = i * 256 + t;
        ob[lin] = fin[lin & 63];
    }
}

// ---------------------------------------------------------------------------
extern "C" void kernel_launch(void* const* d_in, const int* in_sizes, int n_in,
                              void* d_out, int out_size) {
    (void)in_sizes; (void)n_in; (void)out_size;
    const float* Q = (const float*)d_in[0];
    const float* K = (const float*)d_in[1];
    const float* V = (const float*)d_in[2];
    const float* wq1 = (const float*)d_in[3];  const float* bq1 = (const float*)d_in[4];
    const float* wq3 = (const float*)d_in[5];  const float* bq3 = (const float*)d_in[6];
    const float* wq6 = (const float*)d_in[7];  const float* bq6 = (const float*)d_in[8];
    const float* wq9 = (const float*)d_in[9];  const float* bq9 = (const float*)d_in[10];
    const float* wk1 = (const float*)d_in[11]; const float* bk1 = (const float*)d_in[12];
    const float* wk3 = (const float*)d_in[13]; const float* bk3 = (const float*)d_in[14];
    const float* wk6 = (const float*)d_in[15]; const float* bk6 = (const float*)d_in[16];
    const float* wk9 = (const float*)d_in[17]; const float* bk9 = (const float*)d_in[18];
    float* out = (float*)d_out;

    fft512_rows<<<8192, 256>>>(Q, K);
    fft1024_cols<<<1024, 512>>>();

    multiscale<<<dim3(32, 32, 2), 512>>>(wq1, bq1, wq3, bq3, wq6, bq6, wq9, bq9,
                                         wk1, bk1, wk3, bk3, wk6, bk6, wk9, bk9);

    attn_kernel<<<dim3(16, 32, 2), 256>>>(out);   // launch #4 -> profiled

    context_kernel<<<32, 256>>>(V, out);
}